// round 1
// baseline (speedup 1.0000x reference)
#include <cuda_runtime.h>

#define T_DIM 4
#define N_DIM 32
#define C_DIM 512
#define L_DIM 196
#define H_DIM 8
#define D_DIM 64
#define C3 (3 * C_DIM)

// Scratch (device globals: allocation-free per harness rules)
__device__ float g_qkv[(size_t)T_DIM * N_DIM * C3 * L_DIM];      // qkv pre/post LIF (in-place)
__device__ float g_attn[(size_t)T_DIM * N_DIM * C_DIM * L_DIM];  // attn pre/post LIF (in-place)
__device__ float g_proj[(size_t)T_DIM * N_DIM * C_DIM * L_DIM];  // proj+BN pre-LIF

// ---------------------------------------------------------------------------
// Batched GEMM + BatchNorm epilogue.
// out[b, o, l] = BN_o( sum_c W[o,c] * X[b,c,l] )
// Tile: 64(M) x 64(L) x 16(K), 256 threads, 4x4 microtile per thread.
// ---------------------------------------------------------------------------
__global__ __launch_bounds__(256) void gemm_bn_kernel(
    const float* __restrict__ W, const float* __restrict__ X,
    const float* __restrict__ gamma, const float* __restrict__ beta,
    const float* __restrict__ mean, const float* __restrict__ var,
    float* __restrict__ out, int M, int K)
{
    const int L = L_DIM;
    __shared__ float Ws[16][64];  // [k][m] (transposed on store)
    __shared__ float Xs[16][64];  // [k][l]

    const int b = blockIdx.z;
    const int mBase = blockIdx.y * 64;
    const int lBase = blockIdx.x * 64;
    const int tid = threadIdx.x;
    const int tx = tid & 15;       // L microtile
    const int ty = tid >> 4;       // M microtile

    const float* Xb = X + (size_t)b * K * L;

    float acc[4][4];
#pragma unroll
    for (int i = 0; i < 4; i++)
#pragma unroll
        for (int j = 0; j < 4; j++) acc[i][j] = 0.f;

    const int wm = tid >> 2;           // 0..63 (M row for W load)
    const int wk = (tid & 3) * 4;      // K offset (float4)
    const int xk = tid >> 4;           // 0..15 (K row for X load)
    const int xl = (tid & 15) * 4;     // L offset (float4)

    for (int k0 = 0; k0 < K; k0 += 16) {
        __syncthreads();
        // W tile (64m x 16k), transposed into Ws[k][m]
        float4 w4 = *(const float4*)&W[(size_t)(mBase + wm) * K + k0 + wk];
        Ws[wk + 0][wm] = w4.x;
        Ws[wk + 1][wm] = w4.y;
        Ws[wk + 2][wm] = w4.z;
        Ws[wk + 3][wm] = w4.w;
        // X tile (16k x 64l). L=196 is a multiple of 4, rows are 16B-aligned.
        const int gl = lBase + xl;
        if (gl < L) {
            *(float4*)&Xs[xk][xl] = *(const float4*)&Xb[(size_t)(k0 + xk) * L + gl];
        } else {
            *(float4*)&Xs[xk][xl] = make_float4(0.f, 0.f, 0.f, 0.f);
        }
        __syncthreads();

#pragma unroll
        for (int k = 0; k < 16; k++) {
            float4 a = *(const float4*)&Ws[k][ty * 4];
            float4 bb = *(const float4*)&Xs[k][tx * 4];
            float av[4] = {a.x, a.y, a.z, a.w};
            float bv[4] = {bb.x, bb.y, bb.z, bb.w};
#pragma unroll
            for (int i = 0; i < 4; i++)
#pragma unroll
                for (int j = 0; j < 4; j++) acc[i][j] += av[i] * bv[j];
        }
    }

    // BN epilogue
#pragma unroll
    for (int i = 0; i < 4; i++) {
        const int o = mBase + ty * 4 + i;
        const float inv = gamma[o] * rsqrtf(var[o] + 1e-5f);
        const float bias = beta[o] - mean[o] * inv;
#pragma unroll
        for (int j = 0; j < 4; j++) {
            const int l = lBase + tx * 4 + j;
            if (l < L) out[((size_t)b * M + o) * L + l] = acc[i][j] * inv + bias;
        }
    }
}

// ---------------------------------------------------------------------------
// LIF over T=4 (sequential scan per element). In-place safe (each thread owns
// its element across all t). decay = 1/TAU = 0.5.
// ---------------------------------------------------------------------------
__global__ void lif_kernel(const float* __restrict__ in, float* __restrict__ out,
                           int plane, float thr)
{
    const int i = blockIdx.x * blockDim.x + threadIdx.x;
    if (i >= plane) return;
    float v = 0.f;
#pragma unroll
    for (int t = 0; t < T_DIM; t++) {
        const float x = in[(size_t)t * plane + i];
        v += 0.5f * (x - v);
        const float s = (v >= thr) ? 1.f : 0.f;
        out[(size_t)t * plane + i] = s;
        v *= (1.f - s);
    }
}

// ---------------------------------------------------------------------------
// Attention per (t, n, h): vk[d,e] = sum_l v[d,l]*k[e,l]  (exact, dp4a on 0/1
// bytes), then attn[d,l] = SCALE * sum_e vk[d,e]*q[e,l]   (q binary ->
// predicated adds of exact small integers). Writes pre-LIF values.
// ---------------------------------------------------------------------------
__global__ __launch_bounds__(256) void attn_kernel(const float* __restrict__ spk,
                                                   float* __restrict__ outp)
{
    __shared__ unsigned char qc[64 * 196];
    __shared__ unsigned char kc[64 * 196];
    __shared__ unsigned char vc[64 * 196];
    __shared__ unsigned short vk_s[64 * 64];  // [e][d], values <= 196

    const int bx = blockIdx.x;
    const int t = bx >> 8;
    const int n = (bx >> 3) & 31;
    const int h = bx & 7;
    const int tid = threadIdx.x;

    const float* base = spk + ((size_t)(t * N_DIM + n) * C3 + h * D_DIM) * L_DIM;
    const float* qg = base;
    const float* kg = base + (size_t)C_DIM * L_DIM;
    const float* vg = base + (size_t)2 * C_DIM * L_DIM;

    for (int i = tid; i < 64 * 196; i += 256) {
        qc[i] = (unsigned char)(qg[i] != 0.f);
        kc[i] = (unsigned char)(kg[i] != 0.f);
        vc[i] = (unsigned char)(vg[i] != 0.f);
    }
    __syncthreads();

    // vk[e][d] via dp4a: 16 outputs per thread
    {
        const int dd = tid & 63;
        const int e0 = tid >> 6;  // 0..3
        const unsigned* vp = (const unsigned*)(vc + dd * 196);
#pragma unroll
        for (int i = 0; i < 16; i++) {
            const int e = e0 * 16 + i;
            const unsigned* kp = (const unsigned*)(kc + e * 196);
            unsigned sum = 0;
#pragma unroll
            for (int w = 0; w < 49; w++) sum = __dp4a(vp[w], kp[w], sum);
            vk_s[e * 64 + dd] = (unsigned short)sum;
        }
    }
    __syncthreads();

    // attn[d][l] for 49 l's per thread; vk row cached in registers
    const int d = tid & 63;
    const int lg = tid >> 6;  // 0..3; all lanes of a warp share lg -> q broadcast
    float vkreg[64];
#pragma unroll
    for (int e = 0; e < 64; e++) vkreg[e] = (float)vk_s[e * 64 + d];

    float* o = outp + ((size_t)(t * N_DIM + n) * C_DIM + h * D_DIM + d) * L_DIM;
#pragma unroll 1
    for (int li = 0; li < 49; li++) {
        const int l = lg + 4 * li;
        float acc = 0.f;
#pragma unroll
        for (int e = 0; e < 64; e++) {
            if (qc[e * 196 + l]) acc += vkreg[e];
        }
        o[l] = acc * 0.125f;  // SCALE
    }
}

// ---------------------------------------------------------------------------
// Launch
// ---------------------------------------------------------------------------
extern "C" void kernel_launch(void* const* d_in, const int* in_sizes, int n_in,
                              void* d_out, int out_size)
{
    (void)in_sizes; (void)n_in; (void)out_size;
    const float* x_seq      = (const float*)d_in[0];
    const float* qkv_w      = (const float*)d_in[1];
    const float* qkv_gamma  = (const float*)d_in[2];
    const float* qkv_beta   = (const float*)d_in[3];
    const float* qkv_mean   = (const float*)d_in[4];
    const float* qkv_var    = (const float*)d_in[5];
    const float* proj_w     = (const float*)d_in[6];
    const float* proj_gamma = (const float*)d_in[7];
    const float* proj_beta  = (const float*)d_in[8];
    const float* proj_mean  = (const float*)d_in[9];
    const float* proj_var   = (const float*)d_in[10];
    float* out = (float*)d_out;

    float *qkv, *attn, *proj;
    cudaGetSymbolAddress((void**)&qkv, g_qkv);
    cudaGetSymbolAddress((void**)&attn, g_attn);
    cudaGetSymbolAddress((void**)&proj, g_proj);

    const int plane1 = N_DIM * C3 * L_DIM;     // 9,633,792
    const int plane2 = N_DIM * C_DIM * L_DIM;  // 3,211,264

    // 1. QKV GEMM + BN
    dim3 g1(4, C3 / 64, T_DIM * N_DIM);
    gemm_bn_kernel<<<g1, 256>>>(qkv_w, x_seq, qkv_gamma, qkv_beta, qkv_mean,
                                qkv_var, qkv, C3, C_DIM);
    // 2. LIF (thr 1.0) -> spikes in place
    lif_kernel<<<(plane1 + 255) / 256, 256>>>(qkv, qkv, plane1, 1.0f);
    // 3. Attention (exact integer spike math), pre-LIF values
    attn_kernel<<<T_DIM * N_DIM * H_DIM, 256>>>(qkv, attn);
    // 4. LIF (thr 0.5) -> spikes in place
    lif_kernel<<<(plane2 + 255) / 256, 256>>>(attn, attn, plane2, 0.5f);
    // 5. Proj GEMM + BN
    dim3 g2(4, C_DIM / 64, T_DIM * N_DIM);
    gemm_bn_kernel<<<g2, 256>>>(proj_w, attn, proj_gamma, proj_beta, proj_mean,
                                proj_var, proj, C_DIM, C_DIM);
    // 6. LIF (thr 1.0) -> final output
    lif_kernel<<<(plane2 + 255) / 256, 256>>>(proj, out, plane2, 1.0f);
}

// round 2
// speedup vs baseline: 2.7478x; 2.7478x over previous
#include <cuda_runtime.h>
#include <cuda_fp16.h>
#include <cstdint>

#define T_DIM 4
#define N_DIM 32
#define C_DIM 512
#define L_DIM 196
#define LP    200            // padded L (rows 16B-aligned for cp.async)
#define H_DIM 8
#define D_DIM 64
#define C3 (3 * C_DIM)
#define B_DIM (T_DIM * N_DIM)   // 128 batched GEMM problems
#define K_DIM 512

// ---------------------------------------------------------------------------
// Scratch (device globals: allocation-free per harness rules)
// ---------------------------------------------------------------------------
__device__ __half g_xh   [(size_t)B_DIM * K_DIM * LP];          // x_seq fp16, padded
__device__ __half g_wq   [(size_t)C3 * 1024];                   // qkv W hi|lo interleaved per 32-k block
__device__ __half g_wp   [(size_t)C_DIM * 1024];                // proj W split
__device__ float  g_qkv32[(size_t)B_DIM * C3 * L_DIM];          // pre-LIF qkv
__device__ __half g_qkvh [(size_t)B_DIM * C3 * L_DIM];          // qkv spikes fp16 (unpadded)
__device__ float  g_attn32[(size_t)B_DIM * C_DIM * L_DIM];      // pre-LIF attn
__device__ __half g_attnh[(size_t)B_DIM * C_DIM * LP];          // attn spikes fp16, padded
__device__ float  g_proj32[(size_t)B_DIM * C_DIM * L_DIM];      // pre-LIF proj

// ---------------------------------------------------------------------------
// PTX helpers
// ---------------------------------------------------------------------------
__device__ __forceinline__ uint32_t smem_u32(const void* p) {
    return (uint32_t)__cvta_generic_to_shared(p);
}
__device__ __forceinline__ void cp_async16(uint32_t dst, const void* src, int bytes) {
    asm volatile("cp.async.cg.shared.global [%0], [%1], 16, %2;\n"
                 :: "r"(dst), "l"(src), "r"(bytes));
}
__device__ __forceinline__ void cp_commit() {
    asm volatile("cp.async.commit_group;\n");
}
__device__ __forceinline__ void ldsm4(uint32_t (&r)[4], uint32_t addr) {
    asm volatile("ldmatrix.sync.aligned.m8n8.x4.shared.b16 {%0,%1,%2,%3}, [%4];"
                 : "=r"(r[0]), "=r"(r[1]), "=r"(r[2]), "=r"(r[3]) : "r"(addr));
}
__device__ __forceinline__ void ldsm4t(uint32_t (&r)[4], uint32_t addr) {
    asm volatile("ldmatrix.sync.aligned.m8n8.x4.trans.shared.b16 {%0,%1,%2,%3}, [%4];"
                 : "=r"(r[0]), "=r"(r[1]), "=r"(r[2]), "=r"(r[3]) : "r"(addr));
}
__device__ __forceinline__ void mma16816(float* d, const uint32_t* a, const uint32_t* b) {
    asm volatile("mma.sync.aligned.m16n8k16.row.col.f32.f16.f16.f32 "
                 "{%0,%1,%2,%3}, {%4,%5,%6,%7}, {%8,%9}, {%0,%1,%2,%3};"
                 : "+f"(d[0]), "+f"(d[1]), "+f"(d[2]), "+f"(d[3])
                 : "r"(a[0]), "r"(a[1]), "r"(a[2]), "r"(a[3]), "r"(b[0]), "r"(b[1]));
}

// ---------------------------------------------------------------------------
// Conversions
// ---------------------------------------------------------------------------
__global__ void convert_x_kernel(const float* __restrict__ x, __half* __restrict__ xh) {
    const size_t total = (size_t)B_DIM * K_DIM * LP;
    size_t i = (size_t)blockIdx.x * blockDim.x + threadIdx.x;
    if (i >= total) return;
    int l = (int)(i % LP);
    size_t rc = i / LP;
    xh[i] = (l < L_DIM) ? __float2half(x[rc * L_DIM + l]) : __half(0.f);
}

// W split: Ws[o][(k/32)*64 + k%32] = hi, +32 = lo
__global__ void convert_w_kernel(const float* __restrict__ w, __half* __restrict__ ws, int M) {
    int i = blockIdx.x * blockDim.x + threadIdx.x;
    if (i >= M * K_DIM) return;
    int k = i & (K_DIM - 1), o = i >> 9;
    float v = w[i];
    __half hi = __float2half(v);
    __half lo = __float2half(v - __half2float(hi));
    size_t base = (size_t)o * 1024 + (k >> 5) * 64 + (k & 31);
    ws[base] = hi;
    ws[base + 32] = lo;
}

// ---------------------------------------------------------------------------
// Tensor-core GEMM + BN:  out[b,o,l] = BN_o( sum_c W[o,c] X[b,c,l] )
// W pre-split fp16 hi|lo (K effectively 1024), X fp16 spikes [b][512][LP].
// Tile 128(M) x 64(L) x 32(K), double-buffered cp.async, 256 threads.
// ---------------------------------------------------------------------------
#define OT 128
#define LT 64
#define KT 32
#define NSTAGE 16   // 512 / 32

__global__ __launch_bounds__(256, 2) void gemm_tc_kernel(
    const __half* __restrict__ Wsp,   // [M][1024]
    const __half* __restrict__ X,     // [B][512][LP]
    const float* __restrict__ gamma, const float* __restrict__ beta,
    const float* __restrict__ mean,  const float* __restrict__ var,
    float* __restrict__ out, int M)
{
    __shared__ __half sW[2][OT * 64];   // row: 64 halves = 8 chunks of 16B, XOR swizzle
    __shared__ __half sX[2][KT * 64];

    const int b  = blockIdx.z;
    const int o0 = blockIdx.y * OT;
    const int l0 = blockIdx.x * LT;
    const int tid  = threadIdx.x;
    const int warp = tid >> 5, lane = tid & 31;
    const int wm = warp & 3, wn = warp >> 2;   // warp tile 32m x 32n

    const __half* Xb = X + (size_t)b * K_DIM * LP;

    const uint32_t sWa = smem_u32(&sW[0][0]);
    const uint32_t sXa = smem_u32(&sX[0][0]);

    // cp.async source/dst (thread-invariant parts)
    const int wrow = tid >> 1;                // W row 0..127
    const int wcb  = (tid & 1) * 4;           // chunk base
    const int xrow = tid >> 3;                // X k-row 0..31
    const int xch  = tid & 7;                 // X chunk
    const int xl   = l0 + xch * 8;
    const int xbytes = (xl + 8 <= LP) ? 16 : 0;

    float acc[2][4][4];
#pragma unroll
    for (int a = 0; a < 2; a++)
#pragma unroll
        for (int n = 0; n < 4; n++)
#pragma unroll
            for (int j = 0; j < 4; j++) acc[a][n][j] = 0.f;

    auto issue = [&](int s, int buf) {
        const __half* wsrc = Wsp + (size_t)(o0 + wrow) * 1024 + s * 64;
        uint32_t wdst = sWa + (uint32_t)buf * OT * 64 * 2 + wrow * 128;
#pragma unroll
        for (int i = 0; i < 4; i++) {
            int ch = wcb + i;
            cp_async16(wdst + ((ch ^ (wrow & 7)) << 4), wsrc + ch * 8, 16);
        }
        const __half* xsrc = Xb + (size_t)(s * KT + xrow) * LP + xl;
        uint32_t xdst = sXa + (uint32_t)buf * KT * 64 * 2 + xrow * 128 +
                        ((xch ^ (xrow & 7)) << 4);
        cp_async16(xdst, xsrc, xbytes);
    };

    issue(0, 0); cp_commit();
    issue(1, 1); cp_commit();

    // ldmatrix lane geometry
    const int lrow = lane & 15;        // row within 16
    const int lch  = lane >> 4;        // 0/1 -> +8 column chunk

    for (int s = 0; s < NSTAGE; s++) {
        if (s < NSTAGE - 1) asm volatile("cp.async.wait_group 1;\n");
        else                asm volatile("cp.async.wait_group 0;\n");
        __syncthreads();

        const int buf = s & 1;
        const uint32_t sWb = sWa + (uint32_t)buf * OT * 64 * 2;
        const uint32_t sXb = sXa + (uint32_t)buf * KT * 64 * 2;

#pragma unroll
        for (int s2 = 0; s2 < 2; s2++) {           // k16 step within the 32-k stage
            uint32_t Bf[2][4];
#pragma unroll
            for (int i = 0; i < 2; i++) {          // two n16 halves of warp's n32
                int rowB = s2 * 16 + lrow;
                int ch = wn * 4 + i * 2 + lch;
                ldsm4t(Bf[i], sXb + rowB * 128 + ((ch ^ (rowB & 7)) << 4));
            }
#pragma unroll
            for (int p = 0; p < 2; p++) {          // hi / lo weight plane
                uint32_t Af[2][4];
                const int kcol = p * 32 + s2 * 16;
#pragma unroll
                for (int mf = 0; mf < 2; mf++) {
                    int m = wm * 32 + mf * 16 + lrow;
                    int ch = (kcol >> 3) + lch;
                    ldsm4(Af[mf], sWb + m * 128 + ((ch ^ (m & 7)) << 4));
                }
#pragma unroll
                for (int mf = 0; mf < 2; mf++)
#pragma unroll
                    for (int nf = 0; nf < 4; nf++)
                        mma16816(acc[mf][nf], Af[mf], &Bf[nf >> 1][(nf & 1) * 2]);
            }
        }
        __syncthreads();
        if (s + 2 < NSTAGE) { issue(s + 2, buf); cp_commit(); }
    }

    // Epilogue: BN + store (fp32)
#pragma unroll
    for (int mf = 0; mf < 2; mf++) {
#pragma unroll
        for (int dd = 0; dd < 2; dd++) {
            const int o = o0 + wm * 32 + mf * 16 + dd * 8 + (lane >> 2);
            const float inv  = __ldg(&gamma[o]) * rsqrtf(__ldg(&var[o]) + 1e-5f);
            const float bias = __ldg(&beta[o]) - __ldg(&mean[o]) * inv;
            float* orow = out + ((size_t)b * M + o) * L_DIM;
#pragma unroll
            for (int nf = 0; nf < 4; nf++) {
                const int l = l0 + wn * 32 + nf * 8 + (lane & 3) * 2;
                if (l < L_DIM) {
                    float2 v;
                    v.x = acc[mf][nf][dd * 2 + 0] * inv + bias;
                    v.y = acc[mf][nf][dd * 2 + 1] * inv + bias;
                    *(float2*)&orow[l] = v;
                }
            }
        }
    }
}

// ---------------------------------------------------------------------------
// LIF variants (decay = 0.5)
// ---------------------------------------------------------------------------
__global__ void lif_half_kernel(const float* __restrict__ in, __half* __restrict__ out,
                                int plane, float thr)
{
    const int i = blockIdx.x * blockDim.x + threadIdx.x;
    if (i >= plane) return;
    float v = 0.f;
#pragma unroll
    for (int t = 0; t < T_DIM; t++) {
        const float x = in[(size_t)t * plane + i];
        v += 0.5f * (x - v);
        const float s = (v >= thr) ? 1.f : 0.f;
        out[(size_t)t * plane + i] = __float2half(s);
        v *= (1.f - s);
    }
}

__global__ void lif_half_pad_kernel(const float* __restrict__ in, __half* __restrict__ out,
                                    int plane, float thr)
{
    const int i = blockIdx.x * blockDim.x + threadIdx.x;
    if (i >= plane) return;
    const int c = i / L_DIM, l = i % L_DIM;
    const size_t planeP = ((size_t)plane / L_DIM) * LP;
    float v = 0.f;
#pragma unroll
    for (int t = 0; t < T_DIM; t++) {
        const float x = in[(size_t)t * plane + i];
        v += 0.5f * (x - v);
        const float s = (v >= thr) ? 1.f : 0.f;
        out[(size_t)t * planeP + (size_t)c * LP + l] = __float2half(s);
        v *= (1.f - s);
    }
    if (l < LP - L_DIM) {
#pragma unroll
        for (int t = 0; t < T_DIM; t++)
            out[(size_t)t * planeP + (size_t)c * LP + L_DIM + l] = __half(0.f);
    }
}

__global__ void lif_f32_kernel(const float* __restrict__ in, float* __restrict__ out,
                               int plane, float thr)
{
    const int i = blockIdx.x * blockDim.x + threadIdx.x;
    if (i >= plane) return;
    float v = 0.f;
#pragma unroll
    for (int t = 0; t < T_DIM; t++) {
        const float x = in[(size_t)t * plane + i];
        v += 0.5f * (x - v);
        const float s = (v >= thr) ? 1.f : 0.f;
        out[(size_t)t * plane + i] = s;
        v *= (1.f - s);
    }
}

// ---------------------------------------------------------------------------
// Attention per (t, n, h): exact integer spike math via dp4a (unchanged math,
// now reads fp16 spikes).
// ---------------------------------------------------------------------------
__global__ __launch_bounds__(256) void attn_kernel(const __half* __restrict__ spk,
                                                   float* __restrict__ outp)
{
    __shared__ unsigned char qc[64 * 196];
    __shared__ unsigned char kc[64 * 196];
    __shared__ unsigned char vc[64 * 196];
    __shared__ unsigned short vk_s[64 * 64];

    const int bx = blockIdx.x;
    const int t = bx >> 8;
    const int n = (bx >> 3) & 31;
    const int h = bx & 7;
    const int tid = threadIdx.x;

    const unsigned short* base =
        (const unsigned short*)(spk + ((size_t)(t * N_DIM + n) * C3 + h * D_DIM) * L_DIM);
    const unsigned short* qg = base;
    const unsigned short* kg = base + (size_t)C_DIM * L_DIM;
    const unsigned short* vg = base + (size_t)2 * C_DIM * L_DIM;

    for (int i = tid; i < 64 * 196; i += 256) {
        qc[i] = (unsigned char)(qg[i] != 0);
        kc[i] = (unsigned char)(kg[i] != 0);
        vc[i] = (unsigned char)(vg[i] != 0);
    }
    __syncthreads();

    {
        const int dd = tid & 63;
        const int e0 = tid >> 6;
        const unsigned* vp = (const unsigned*)(vc + dd * 196);
#pragma unroll
        for (int i = 0; i < 16; i++) {
            const int e = e0 * 16 + i;
            const unsigned* kp = (const unsigned*)(kc + e * 196);
            unsigned sum = 0;
#pragma unroll
            for (int w = 0; w < 49; w++) sum = __dp4a(vp[w], kp[w], sum);
            vk_s[e * 64 + dd] = (unsigned short)sum;
        }
    }
    __syncthreads();

    const int d = tid & 63;
    const int lg = tid >> 6;
    float vkreg[64];
#pragma unroll
    for (int e = 0; e < 64; e++) vkreg[e] = (float)vk_s[e * 64 + d];

    float* o = outp + ((size_t)(t * N_DIM + n) * C_DIM + h * D_DIM + d) * L_DIM;
#pragma unroll 1
    for (int li = 0; li < 49; li++) {
        const int l = lg + 4 * li;
        float acc = 0.f;
#pragma unroll
        for (int e = 0; e < 64; e++) {
            if (qc[e * 196 + l]) acc += vkreg[e];
        }
        o[l] = acc * 0.125f;
    }
}

// ---------------------------------------------------------------------------
// Launch
// ---------------------------------------------------------------------------
extern "C" void kernel_launch(void* const* d_in, const int* in_sizes, int n_in,
                              void* d_out, int out_size)
{
    (void)in_sizes; (void)n_in; (void)out_size;
    const float* x_seq      = (const float*)d_in[0];
    const float* qkv_w      = (const float*)d_in[1];
    const float* qkv_gamma  = (const float*)d_in[2];
    const float* qkv_beta   = (const float*)d_in[3];
    const float* qkv_mean   = (const float*)d_in[4];
    const float* qkv_var    = (const float*)d_in[5];
    const float* proj_w     = (const float*)d_in[6];
    const float* proj_gamma = (const float*)d_in[7];
    const float* proj_beta  = (const float*)d_in[8];
    const float* proj_mean  = (const float*)d_in[9];
    const float* proj_var   = (const float*)d_in[10];
    float* out = (float*)d_out;

    __half *xh, *wq, *wp, *qkvh, *attnh;
    float *qkv32, *attn32, *proj32;
    cudaGetSymbolAddress((void**)&xh, g_xh);
    cudaGetSymbolAddress((void**)&wq, g_wq);
    cudaGetSymbolAddress((void**)&wp, g_wp);
    cudaGetSymbolAddress((void**)&qkv32, g_qkv32);
    cudaGetSymbolAddress((void**)&qkvh, g_qkvh);
    cudaGetSymbolAddress((void**)&attn32, g_attn32);
    cudaGetSymbolAddress((void**)&attnh, g_attnh);
    cudaGetSymbolAddress((void**)&proj32, g_proj32);

    const int plane1 = N_DIM * C3 * L_DIM;     // 9,633,792
    const int plane2 = N_DIM * C_DIM * L_DIM;  // 3,211,264

    // 0. Weight split + input conversion
    convert_w_kernel<<<(C3 * K_DIM + 255) / 256, 256>>>(qkv_w, wq, C3);
    convert_w_kernel<<<(C_DIM * K_DIM + 255) / 256, 256>>>(proj_w, wp, C_DIM);
    {
        size_t tot = (size_t)B_DIM * K_DIM * LP;
        convert_x_kernel<<<(unsigned)((tot + 255) / 256), 256>>>(x_seq, xh);
    }

    // 1. QKV GEMM + BN (tensor cores, fp16 hi/lo split)
    dim3 g1(4, C3 / OT, B_DIM);
    gemm_tc_kernel<<<g1, 256>>>(wq, xh, qkv_gamma, qkv_beta, qkv_mean, qkv_var,
                                qkv32, C3);
    // 2. LIF (thr 1.0) -> fp16 spikes
    lif_half_kernel<<<(plane1 + 255) / 256, 256>>>(qkv32, qkvh, plane1, 1.0f);
    // 3. Attention (exact integer spike math)
    attn_kernel<<<T_DIM * N_DIM * H_DIM, 256>>>(qkvh, attn32);
    // 4. LIF (thr 0.5) -> fp16 spikes, padded L
    lif_half_pad_kernel<<<(plane2 + 255) / 256, 256>>>(attn32, attnh, plane2, 0.5f);
    // 5. Proj GEMM + BN
    dim3 g2(4, C_DIM / OT, B_DIM);
    gemm_tc_kernel<<<g2, 256>>>(wp, attnh, proj_gamma, proj_beta, proj_mean,
                                proj_var, proj32, C_DIM);
    // 6. LIF (thr 1.0) -> final fp32 output
    lif_f32_kernel<<<(plane2 + 255) / 256, 256>>>(proj32, out, plane2, 1.0f);
}

// round 3
// speedup vs baseline: 3.3260x; 1.2104x over previous
#include <cuda_runtime.h>
#include <cuda_fp16.h>
#include <cstdint>

#define T_DIM 4
#define N_DIM 32
#define C_DIM 512
#define L_DIM 196
#define H_DIM 8
#define D_DIM 64
#define C3 (3 * C_DIM)
#define B_DIM (T_DIM * N_DIM)     // 128
#define K_DIM 512
#define NCOL (B_DIM * L_DIM)      // 25088 = 392 * 64 (no padding!)
#define TSTRIDE (N_DIM * L_DIM)   // 6272: column stride between timesteps

// ---------------------------------------------------------------------------
// Scratch (device globals: allocation-free per harness rules)
// Activations live as [rows][NCOL] matrices, column index = (t*32+n)*196 + l.
// ---------------------------------------------------------------------------
__device__ __half g_xh    [(size_t)K_DIM * NCOL];    // x_seq fp16 [512][25088]
__device__ __half g_wq    [(size_t)C3 * 1024];       // qkv W hi|lo split
__device__ __half g_wp    [(size_t)C_DIM * 1024];    // proj W split
__device__ float  g_qkv32 [(size_t)C3 * NCOL];       // pre-LIF qkv
__device__ __half g_qkvh  [(size_t)C3 * NCOL];       // qkv spikes fp16
__device__ float  g_attn32[(size_t)C_DIM * NCOL];    // pre-LIF attn
__device__ __half g_attnh [(size_t)C_DIM * NCOL];    // attn spikes fp16
__device__ float  g_proj32[(size_t)C_DIM * NCOL];    // pre-LIF proj

// ---------------------------------------------------------------------------
// PTX helpers
// ---------------------------------------------------------------------------
__device__ __forceinline__ uint32_t smem_u32(const void* p) {
    return (uint32_t)__cvta_generic_to_shared(p);
}
__device__ __forceinline__ void cp_async16(uint32_t dst, const void* src) {
    asm volatile("cp.async.cg.shared.global [%0], [%1], 16;\n" :: "r"(dst), "l"(src));
}
__device__ __forceinline__ void cp_commit() {
    asm volatile("cp.async.commit_group;\n");
}
__device__ __forceinline__ void ldsm4(uint32_t (&r)[4], uint32_t addr) {
    asm volatile("ldmatrix.sync.aligned.m8n8.x4.shared.b16 {%0,%1,%2,%3}, [%4];"
                 : "=r"(r[0]), "=r"(r[1]), "=r"(r[2]), "=r"(r[3]) : "r"(addr));
}
__device__ __forceinline__ void ldsm4t(uint32_t (&r)[4], uint32_t addr) {
    asm volatile("ldmatrix.sync.aligned.m8n8.x4.trans.shared.b16 {%0,%1,%2,%3}, [%4];"
                 : "=r"(r[0]), "=r"(r[1]), "=r"(r[2]), "=r"(r[3]) : "r"(addr));
}
__device__ __forceinline__ void mma16816(float* d, const uint32_t* a, const uint32_t* b) {
    asm volatile("mma.sync.aligned.m16n8k16.row.col.f32.f16.f16.f32 "
                 "{%0,%1,%2,%3}, {%4,%5,%6,%7}, {%8,%9}, {%0,%1,%2,%3};"
                 : "+f"(d[0]), "+f"(d[1]), "+f"(d[2]), "+f"(d[3])
                 : "r"(a[0]), "r"(a[1]), "r"(a[2]), "r"(a[3]), "r"(b[0]), "r"(b[1]));
}

// ---------------------------------------------------------------------------
// Conversions
// ---------------------------------------------------------------------------
// x [b][c][l] (f32) -> xh [c][b*196+l] (f16). Reads and writes coalesced in l.
__global__ void convert_x_kernel(const float* __restrict__ x, __half* __restrict__ xh) {
    const size_t total = (size_t)B_DIM * K_DIM * L_DIM;
    size_t i = (size_t)blockIdx.x * blockDim.x + threadIdx.x;
    if (i >= total) return;
    int l = (int)(i % L_DIM);
    int c = (int)((i / L_DIM) % K_DIM);
    int b = (int)(i / ((size_t)L_DIM * K_DIM));
    xh[(size_t)c * NCOL + b * L_DIM + l] = __float2half(x[i]);
}

// W split: Ws[o][(k/32)*64 + k%32] = hi, +32 = lo  (exact: hi + lo == W in f32)
__global__ void convert_w_kernel(const float* __restrict__ w, __half* __restrict__ ws, int M) {
    int i = blockIdx.x * blockDim.x + threadIdx.x;
    if (i >= M * K_DIM) return;
    int k = i & (K_DIM - 1), o = i >> 9;
    float v = w[i];
    __half hi = __float2half(v);
    __half lo = __float2half(v - __half2float(hi));
    size_t base = (size_t)o * 1024 + (k >> 5) * 64 + (k & 31);
    ws[base] = hi;
    ws[base + 32] = lo;
}

// ---------------------------------------------------------------------------
// Tensor-core GEMM + BN:  out[o, col] = BN_o( sum_c W[o,c] X[c, col] )
// W pre-split fp16 hi|lo (K effectively 1024), X fp16 [512][25088].
// Tile 128(M) x 64(N) x 32(K), 4-stage cp.async pipeline, 256 threads.
// ---------------------------------------------------------------------------
#define OT 128
#define LT 64
#define KT 32
#define NSTAGE 16                  // 512 / 32
#define STG 4
#define STG_BYTES (OT * 64 * 2 + KT * 64 * 2)   // 20480 (W tile + X tile)

__global__ __launch_bounds__(256, 2) void gemm_tc_kernel(
    const __half* __restrict__ Wsp,   // [M][1024]
    const __half* __restrict__ X,     // [512][NCOL]
    const float* __restrict__ gamma, const float* __restrict__ beta,
    const float* __restrict__ mean,  const float* __restrict__ var,
    float* __restrict__ out, int M)
{
    extern __shared__ __half sm[];
    const uint32_t sBase = smem_u32(sm);

    const int o0 = blockIdx.y * OT;
    const int c0 = blockIdx.x * LT;
    const int tid  = threadIdx.x;
    const int warp = tid >> 5, lane = tid & 31;
    const int wm = warp & 3, wn = warp >> 2;   // warp tile 32m x 32n

    // cp.async geometry (thread-invariant)
    const int wrow = tid >> 1;                // W row 0..127
    const int wcb  = (tid & 1) * 4;           // chunk base (4 x 16B per thread)
    const int xrow = tid >> 3;                // X k-row 0..31
    const int xch  = tid & 7;                 // X chunk (16B)

    float acc[2][4][4];
#pragma unroll
    for (int a = 0; a < 2; a++)
#pragma unroll
        for (int n = 0; n < 4; n++)
#pragma unroll
            for (int j = 0; j < 4; j++) acc[a][n][j] = 0.f;

    auto issue = [&](int s) {
        const uint32_t sb = sBase + (uint32_t)(s & (STG - 1)) * STG_BYTES;
        const __half* wsrc = Wsp + (size_t)(o0 + wrow) * 1024 + s * 64;
        const uint32_t wdst = sb + wrow * 128;
#pragma unroll
        for (int i = 0; i < 4; i++) {
            int ch = wcb + i;
            cp_async16(wdst + ((ch ^ (wrow & 7)) << 4), wsrc + ch * 8);
        }
        const __half* xsrc = X + (size_t)(s * KT + xrow) * NCOL + c0 + xch * 8;
        const uint32_t xdst = sb + OT * 128 + xrow * 128 + ((xch ^ (xrow & 7)) << 4);
        cp_async16(xdst, xsrc);
        cp_commit();
    };

    issue(0); issue(1); issue(2);

    const int lrow = lane & 15;        // ldmatrix row within 16
    const int lch  = lane >> 4;        // 0/1 -> +8 column chunk

    for (int s = 0; s < NSTAGE; s++) {
        const int rem = NSTAGE - 1 - s;
        if (rem >= 2)      asm volatile("cp.async.wait_group 2;\n");
        else if (rem == 1) asm volatile("cp.async.wait_group 1;\n");
        else               asm volatile("cp.async.wait_group 0;\n");
        __syncthreads();

        const uint32_t sWb = sBase + (uint32_t)(s & (STG - 1)) * STG_BYTES;
        const uint32_t sXb = sWb + OT * 128;

#pragma unroll
        for (int s2 = 0; s2 < 2; s2++) {           // k16 step within the 32-k stage
            uint32_t Bf[2][4];
#pragma unroll
            for (int i = 0; i < 2; i++) {          // two n16 halves of warp's n32
                int rowB = s2 * 16 + lrow;
                int ch = wn * 4 + i * 2 + lch;
                ldsm4t(Bf[i], sXb + rowB * 128 + ((ch ^ (rowB & 7)) << 4));
            }
#pragma unroll
            for (int p = 0; p < 2; p++) {          // hi / lo weight plane
                uint32_t Af[2][4];
                const int kcol = p * 32 + s2 * 16;
#pragma unroll
                for (int mf = 0; mf < 2; mf++) {
                    int m = wm * 32 + mf * 16 + lrow;
                    int ch = (kcol >> 3) + lch;
                    ldsm4(Af[mf], sWb + m * 128 + ((ch ^ (m & 7)) << 4));
                }
#pragma unroll
                for (int mf = 0; mf < 2; mf++)
#pragma unroll
                    for (int nf = 0; nf < 4; nf++)
                        mma16816(acc[mf][nf], Af[mf], &Bf[nf >> 1][(nf & 1) * 2]);
            }
        }
        if (s + 3 < NSTAGE) issue(s + 3);
    }

    // Epilogue: BN + store (fp32). NCOL is a multiple of 64 -> no bounds checks.
#pragma unroll
    for (int mf = 0; mf < 2; mf++) {
#pragma unroll
        for (int dd = 0; dd < 2; dd++) {
            const int o = o0 + wm * 32 + mf * 16 + dd * 8 + (lane >> 2);
            const float inv  = __ldg(&gamma[o]) * rsqrtf(__ldg(&var[o]) + 1e-5f);
            const float bias = __ldg(&beta[o]) - __ldg(&mean[o]) * inv;
            float* orow = out + (size_t)o * NCOL;
#pragma unroll
            for (int nf = 0; nf < 4; nf++) {
                const int col = c0 + wn * 32 + nf * 8 + (lane & 3) * 2;
                float2 v;
                v.x = acc[mf][nf][dd * 2 + 0] * inv + bias;
                v.y = acc[mf][nf][dd * 2 + 1] * inv + bias;
                *(float2*)&orow[col] = v;
            }
        }
    }
}

// ---------------------------------------------------------------------------
// LIF over T=4 on [Mrows][NCOL] matrices; timestep = column offset t*TSTRIDE.
// ---------------------------------------------------------------------------
__global__ void lif_mat_kernel(const float* __restrict__ in, __half* __restrict__ out,
                               int total, float thr)   // total = Mrows * TSTRIDE
{
    const int i = blockIdx.x * blockDim.x + threadIdx.x;
    if (i >= total) return;
    const int o = i / TSTRIDE, r = i % TSTRIDE;
    const size_t base = (size_t)o * NCOL + r;
    float v = 0.f;
#pragma unroll
    for (int t = 0; t < T_DIM; t++) {
        const float x = in[base + t * TSTRIDE];
        v += 0.5f * (x - v);
        const float s = (v >= thr) ? 1.f : 0.f;
        out[base + t * TSTRIDE] = __float2half(s);
        v *= (1.f - s);
    }
}

// Final LIF: [512][NCOL] -> standard output layout [t][n][c][l] (f32)
__global__ void lif_final_kernel(const float* __restrict__ in, float* __restrict__ out,
                                 float thr)
{
    const int i = blockIdx.x * blockDim.x + threadIdx.x;
    if (i >= C_DIM * TSTRIDE) return;
    const int c = i / TSTRIDE, r = i % TSTRIDE;
    const int n = r / L_DIM, l = r % L_DIM;
    const size_t base = (size_t)c * NCOL + r;
    float v = 0.f;
#pragma unroll
    for (int t = 0; t < T_DIM; t++) {
        const float x = in[base + t * TSTRIDE];
        v += 0.5f * (x - v);
        const float s = (v >= thr) ? 1.f : 0.f;
        out[(((size_t)(t * N_DIM + n)) * C_DIM + c) * L_DIM + l] = s;
        v *= (1.f - s);
    }
}

// ---------------------------------------------------------------------------
// Attention per (t, n, h): vk = V.K^T exact via dp4a on 0/1 bytes, then
// attn = SCALE * vk.Q via predicated adds. Reads fp16 spikes [1536][NCOL].
// ---------------------------------------------------------------------------
__global__ __launch_bounds__(256) void attn_kernel(const __half* __restrict__ spk,
                                                   float* __restrict__ outp)
{
    __shared__ unsigned char qc[64 * 196];
    __shared__ unsigned char kc[64 * 196];
    __shared__ unsigned char vc[64 * 196];
    __shared__ unsigned short vk_s[64 * 64];

    const int bx = blockIdx.x;
    const int t = bx >> 8;
    const int n = (bx >> 3) & 31;
    const int h = bx & 7;
    const int tid = threadIdx.x;

    const size_t colOff = (size_t)(t * N_DIM + n) * L_DIM;
    const unsigned short* qg = (const unsigned short*)spk + (size_t)(h * D_DIM) * NCOL + colOff;
    const unsigned short* kg = qg + (size_t)C_DIM * NCOL;
    const unsigned short* vg = qg + (size_t)2 * C_DIM * NCOL;

    for (int i = tid; i < 64 * 196; i += 256) {
        const int d = i / 196, l = i - d * 196;
        const size_t a = (size_t)d * NCOL + l;
        qc[i] = (unsigned char)(qg[a] != 0);
        kc[i] = (unsigned char)(kg[a] != 0);
        vc[i] = (unsigned char)(vg[a] != 0);
    }
    __syncthreads();

    {
        const int dd = tid & 63;
        const int e0 = tid >> 6;
        const unsigned* vp = (const unsigned*)(vc + dd * 196);
#pragma unroll
        for (int i = 0; i < 16; i++) {
            const int e = e0 * 16 + i;
            const unsigned* kp = (const unsigned*)(kc + e * 196);
            unsigned sum = 0;
#pragma unroll
            for (int w = 0; w < 49; w++) sum = __dp4a(vp[w], kp[w], sum);
            vk_s[e * 64 + dd] = (unsigned short)sum;
        }
    }
    __syncthreads();

    const int d = tid & 63;
    const int lg = tid >> 6;
    float vkreg[64];
#pragma unroll
    for (int e = 0; e < 64; e++) vkreg[e] = (float)vk_s[e * 64 + d];

    float* o = outp + (size_t)(h * D_DIM + d) * NCOL + colOff;
#pragma unroll 1
    for (int li = 0; li < 49; li++) {
        const int l = lg + 4 * li;
        float acc = 0.f;
#pragma unroll
        for (int e = 0; e < 64; e++) {
            if (qc[e * 196 + l]) acc += vkreg[e];
        }
        o[l] = acc * 0.125f;
    }
}

// ---------------------------------------------------------------------------
// Launch
// ---------------------------------------------------------------------------
extern "C" void kernel_launch(void* const* d_in, const int* in_sizes, int n_in,
                              void* d_out, int out_size)
{
    (void)in_sizes; (void)n_in; (void)out_size;
    const float* x_seq      = (const float*)d_in[0];
    const float* qkv_w      = (const float*)d_in[1];
    const float* qkv_gamma  = (const float*)d_in[2];
    const float* qkv_beta   = (const float*)d_in[3];
    const float* qkv_mean   = (const float*)d_in[4];
    const float* qkv_var    = (const float*)d_in[5];
    const float* proj_w     = (const float*)d_in[6];
    const float* proj_gamma = (const float*)d_in[7];
    const float* proj_beta  = (const float*)d_in[8];
    const float* proj_mean  = (const float*)d_in[9];
    const float* proj_var   = (const float*)d_in[10];
    float* out = (float*)d_out;

    __half *xh, *wq, *wp, *qkvh, *attnh;
    float *qkv32, *attn32, *proj32;
    cudaGetSymbolAddress((void**)&xh, g_xh);
    cudaGetSymbolAddress((void**)&wq, g_wq);
    cudaGetSymbolAddress((void**)&wp, g_wp);
    cudaGetSymbolAddress((void**)&qkv32, g_qkv32);
    cudaGetSymbolAddress((void**)&qkvh, g_qkvh);
    cudaGetSymbolAddress((void**)&attn32, g_attn32);
    cudaGetSymbolAddress((void**)&attnh, g_attnh);
    cudaGetSymbolAddress((void**)&proj32, g_proj32);

    static bool attr_done = false;
    if (!attr_done) {
        cudaFuncSetAttribute(gemm_tc_kernel,
                             cudaFuncAttributeMaxDynamicSharedMemorySize,
                             STG * STG_BYTES);
        attr_done = true;
    }
    const int smemB = STG * STG_BYTES;   // 81920

    // 0. Weight split + input conversion
    convert_w_kernel<<<(C3 * K_DIM + 255) / 256, 256>>>(qkv_w, wq, C3);
    convert_w_kernel<<<(C_DIM * K_DIM + 255) / 256, 256>>>(proj_w, wp, C_DIM);
    {
        size_t tot = (size_t)B_DIM * K_DIM * L_DIM;
        convert_x_kernel<<<(unsigned)((tot + 255) / 256), 256>>>(x_seq, xh);
    }

    // 1. QKV GEMM + BN: [1536][25088]
    dim3 g1(NCOL / LT, C3 / OT);
    gemm_tc_kernel<<<g1, 256, smemB>>>(wq, xh, qkv_gamma, qkv_beta, qkv_mean,
                                       qkv_var, qkv32, C3);
    // 2. LIF (thr 1.0) -> fp16 spikes
    lif_mat_kernel<<<(C3 * TSTRIDE + 255) / 256, 256>>>(qkv32, qkvh,
                                                        C3 * TSTRIDE, 1.0f);
    // 3. Attention (exact integer spike math)
    attn_kernel<<<T_DIM * N_DIM * H_DIM, 256>>>(qkvh, attn32);
    // 4. LIF (thr 0.5) -> fp16 spikes
    lif_mat_kernel<<<(C_DIM * TSTRIDE + 255) / 256, 256>>>(attn32, attnh,
                                                           C_DIM * TSTRIDE, 0.5f);
    // 5. Proj GEMM + BN: [512][25088]
    dim3 g2(NCOL / LT, C_DIM / OT);
    gemm_tc_kernel<<<g2, 256, smemB>>>(wp, attnh, proj_gamma, proj_beta,
                                       proj_mean, proj_var, proj32, C_DIM);
    // 6. LIF (thr 1.0) -> final fp32 output
    lif_final_kernel<<<(C_DIM * TSTRIDE + 255) / 256, 256>>>(proj32, out, 1.0f);
}